// round 10
// baseline (speedup 1.0000x reference)
#include <cuda_runtime.h>
#include <cuda_fp16.h>
#include <cstdint>

#define NB 32
#define NN 1024
#define NM 1024
#define NITER 500
#define CONV_TOL 2e-3f

// ---------------- device scratch (allocation-free) ----------------
// K' = fp16(256 * exp(-10*C)); scale keeps all values in fp16 normal range.
static __device__ __align__(128) __half g_K[(size_t)NB * NN * NM]; // 64 MB fp16
static __device__ __align__(16) float g_u[NB * NN];   // u' = u/256 (scale-invariant outputs)
static __device__ __align__(16) float g_v[NB * NM];
static __device__ __align__(16) float g_part[NB * 32];
static __device__ __align__(16) int g_flag[NB * 4];
static __device__ __align__(16) unsigned g_cnt[NB];

__device__ __forceinline__ void cluster_sync_() {
    asm volatile("barrier.cluster.arrive.aligned;\n\t"
                 "barrier.cluster.wait.aligned;" ::: "memory");
}

// 256*exp(-10c) = exp(-10c + ln 256)
__device__ __forceinline__ uint2 pack_kf4(float4 c) {
    const float LN256 = 5.545177444479562f;
    float k0 = __expf(fmaf(-10.0f, c.x, LN256));
    float k1 = __expf(fmaf(-10.0f, c.y, LN256));
    float k2 = __expf(fmaf(-10.0f, c.z, LN256));
    float k3 = __expf(fmaf(-10.0f, c.w, LN256));
    __half2 h01 = __floats2half2_rn(k0, k1);
    __half2 h23 = __floats2half2_rn(k2, k3);
    uint2 o;
    o.x = *reinterpret_cast<unsigned*>(&h01);
    o.y = *reinterpret_cast<unsigned*>(&h23);
    return o;
}

// ---------------- precompute: K' fp16, u0 = 1, C passthrough ----------------
__global__ void prep_kernel(const float4* __restrict__ C4, float4* __restrict__ outC4) {
    const size_t total4 = (size_t)NB * NN * NM / 4;
    const size_t stride = (size_t)gridDim.x * blockDim.x;
    const size_t gtid = (size_t)blockIdx.x * blockDim.x + threadIdx.x;
    uint2* K2 = reinterpret_cast<uint2*>(g_K);
    for (size_t i = gtid; i < total4; i += 4 * stride) {
        float4 c0 = __ldcs(&C4[i]);
        float4 c1 = __ldcs(&C4[i + stride]);
        float4 c2 = __ldcs(&C4[i + 2 * stride]);
        float4 c3 = __ldcs(&C4[i + 3 * stride]);
        __stcs(&outC4[i], c0);
        __stcs(&outC4[i + stride], c1);
        __stcs(&outC4[i + 2 * stride], c2);
        __stcs(&outC4[i + 3 * stride], c3);
        K2[i] = pack_kf4(c0);
        K2[i + stride] = pack_kf4(c1);
        K2[i + 2 * stride] = pack_kf4(c2);
        K2[i + 3 * stride] = pack_kf4(c3);
    }
    for (size_t j = gtid; j < (size_t)NB * NN; j += stride)
        g_u[j] = 1.0f;
    if (gtid < NB) g_cnt[gtid] = 0;
}

// ---------------- persistent Sinkhorn iteration kernel ----------------
// grid = 128 CTAs x 512 threads, cluster (4,1,1): 4 CTAs per batch.
extern "C" __global__ void __cluster_dims__(4, 1, 1) __launch_bounds__(512, 1)
sink_iter(const float* __restrict__ d1, const float* __restrict__ d2) {
    __shared__ float s_vec[NM];
    __shared__ float s_red[16 * 256];
    __shared__ float s_uown[256];
    __shared__ int s_flag;
    __shared__ int s_break;

    const int b = blockIdx.x >> 2;
    const int cr = blockIdx.x & 3;
    const int tid = threadIdx.x;
    const int lane = tid & 31;
    const int warp = tid >> 5;

    const __half* Kbatch = g_K + (size_t)b * NN * NM;
    const float* d1b = d1 + b * NN;
    const float* d2b = d2 + b * NM;
    const int mbase = cr * 256;
    const int nbase = cr * 256;

    for (int it = 0; it < NITER; ++it) {
        // ---- Phase A: v[mbase + 0..255] = d2 / (K'^T u) ----
        for (int i = tid; i < NN; i += 512) s_vec[i] = __ldcg(&g_u[b * NN + i]);
        __syncthreads();
        if (tid < 256) s_uown[tid] = s_vec[nbase + tid];
        if (tid == 0) s_flag = 0;
        {
            const __half* Kc = Kbatch + mbase + lane * 8;
            float acc[8];
#pragma unroll
            for (int j = 0; j < 8; ++j) acc[j] = 0.0f;
            for (int n = warp; n < NN; n += 64) {
                uint4 kv0 = *reinterpret_cast<const uint4*>(Kc + (size_t)(n) * NM);
                uint4 kv1 = *reinterpret_cast<const uint4*>(Kc + (size_t)(n + 16) * NM);
                uint4 kv2 = *reinterpret_cast<const uint4*>(Kc + (size_t)(n + 32) * NM);
                uint4 kv3 = *reinterpret_cast<const uint4*>(Kc + (size_t)(n + 48) * NM);
                float u0 = s_vec[n];
                float u1 = s_vec[n + 16];
                float u2 = s_vec[n + 32];
                float u3 = s_vec[n + 48];
#define FMA8(kv, uu)                                                              \
                {                                                                  \
                    float2 f0 = __half22float2(*reinterpret_cast<const __half2*>(&kv.x)); \
                    float2 f1 = __half22float2(*reinterpret_cast<const __half2*>(&kv.y)); \
                    float2 f2 = __half22float2(*reinterpret_cast<const __half2*>(&kv.z)); \
                    float2 f3 = __half22float2(*reinterpret_cast<const __half2*>(&kv.w)); \
                    acc[0] = fmaf(f0.x, uu, acc[0]);                               \
                    acc[1] = fmaf(f0.y, uu, acc[1]);                               \
                    acc[2] = fmaf(f1.x, uu, acc[2]);                               \
                    acc[3] = fmaf(f1.y, uu, acc[3]);                               \
                    acc[4] = fmaf(f2.x, uu, acc[4]);                               \
                    acc[5] = fmaf(f2.y, uu, acc[5]);                               \
                    acc[6] = fmaf(f3.x, uu, acc[6]);                               \
                    acc[7] = fmaf(f3.y, uu, acc[7]);                               \
                }
                FMA8(kv0, u0)
                FMA8(kv1, u1)
                FMA8(kv2, u2)
                FMA8(kv3, u3)
            }
#pragma unroll
            for (int j = 0; j < 8; ++j) s_red[warp * 256 + lane * 8 + j] = acc[j];
        }
        __syncthreads();
        if (tid < 256) {
            float s = 0.0f;
#pragma unroll
            for (int g = 0; g < 16; ++g) s += s_red[g * 256 + tid];
            float v = d2b[mbase + tid] / s;
            __stcg(&g_v[b * NM + mbase + tid], v);
        }
        __syncthreads();
        cluster_sync_();

        // ---- Phase B: u[nbase + 0..255] = d1 / (K' v) ----
        for (int i = tid; i < NM; i += 512) s_vec[i] = __ldcg(&g_v[b * NM + i]);
        __syncthreads();
        {
            const int row0w = nbase + warp * 16;
#pragma unroll
            for (int g = 0; g < 4; ++g) {
                const int r0 = row0w + g * 4;
                const __half* Kr = Kbatch + (size_t)r0 * NM + lane * 8;
                float a[4] = {0.0f, 0.0f, 0.0f, 0.0f};
#pragma unroll
                for (int k = 0; k < 4; ++k) {
                    const int c0 = k * 256 + lane * 8;
                    float4 va = *reinterpret_cast<const float4*>(&s_vec[c0]);
                    float4 vb = *reinterpret_cast<const float4*>(&s_vec[c0 + 4]);
                    uint4 kq0 = *reinterpret_cast<const uint4*>(Kr + (size_t)0 * NM + k * 256);
                    uint4 kq1 = *reinterpret_cast<const uint4*>(Kr + (size_t)1 * NM + k * 256);
                    uint4 kq2 = *reinterpret_cast<const uint4*>(Kr + (size_t)2 * NM + k * 256);
                    uint4 kq3 = *reinterpret_cast<const uint4*>(Kr + (size_t)3 * NM + k * 256);
#define ROWFMA(r, kv)                                                              \
                    {                                                               \
                        float2 f0 = __half22float2(*reinterpret_cast<const __half2*>(&kv.x)); \
                        float2 f1 = __half22float2(*reinterpret_cast<const __half2*>(&kv.y)); \
                        float2 f2 = __half22float2(*reinterpret_cast<const __half2*>(&kv.z)); \
                        float2 f3 = __half22float2(*reinterpret_cast<const __half2*>(&kv.w)); \
                        float ar = a[r];                                            \
                        ar = fmaf(f0.x, va.x, ar);                                  \
                        ar = fmaf(f0.y, va.y, ar);                                  \
                        ar = fmaf(f1.x, va.z, ar);                                  \
                        ar = fmaf(f1.y, va.w, ar);                                  \
                        ar = fmaf(f2.x, vb.x, ar);                                  \
                        ar = fmaf(f2.y, vb.y, ar);                                  \
                        ar = fmaf(f3.x, vb.z, ar);                                  \
                        ar = fmaf(f3.y, vb.w, ar);                                  \
                        a[r] = ar;                                                  \
                    }
                    ROWFMA(0, kq0)
                    ROWFMA(1, kq1)
                    ROWFMA(2, kq2)
                    ROWFMA(3, kq3)
                }
#pragma unroll
                for (int off = 16; off; off >>= 1) {
#pragma unroll
                    for (int r = 0; r < 4; ++r) a[r] += __shfl_xor_sync(0xffffffffu, a[r], off);
                }
                if (lane < 4) {
                    float un = d1b[r0 + lane] / a[lane];
                    __stcg(&g_u[b * NN + r0 + lane], un);
                    float uold = s_uown[warp * 16 + g * 4 + lane];
                    if (fabsf(un - uold) > CONV_TOL * fabsf(un)) s_flag = 1;
                }
            }
        }
        __syncthreads();
        if (tid == 0) __stcg(&g_flag[blockIdx.x], s_flag);
        cluster_sync_();
        if (tid == 0) {
            int base = (b << 2);
            int f = __ldcg(&g_flag[base]) | __ldcg(&g_flag[base + 1]) |
                    __ldcg(&g_flag[base + 2]) | __ldcg(&g_flag[base + 3]);
            s_break = (f == 0);
        }
        __syncthreads();
        if (s_break) break;
    }
}

// ---------------- finalize: T = u' * K' * v (no exp!), fused dists = sum(C*T) --------
// 1024 blocks x 256 threads; block = 32 rows of one batch. K' is L2-resident.
__global__ void __launch_bounds__(256) finalize_kernel(const float4* __restrict__ C4,
                                                       float4* __restrict__ T4,
                                                       float* __restrict__ outD) {
    const int bid = blockIdx.x;
    const int b = bid >> 5;
    const int chunk = bid & 31;
    const int tid = threadIdx.x;

    __shared__ float s_u[32];
    __shared__ float s_v[NM];
    __shared__ float s_red[256];

    if (tid < 32) s_u[tid] = __ldcg(&g_u[b * NN + chunk * 32 + tid]);
    for (int i = tid; i < NM; i += 256) s_v[i] = __ldcg(&g_v[b * NM + i]);
    __syncthreads();

    const size_t base = (size_t)b * (NN * NM / 4) + (size_t)chunk * 8192;
    const uint2* K2 = reinterpret_cast<const uint2*>(g_K);  // uint2 = 4 fp16, same idx as float4
    float local = 0.0f;
#pragma unroll
    for (int step = 0; step < 8; ++step) {
        const int j0 = step * 1024 + tid;
        float4 c0 = __ldcs(&C4[base + j0]);
        float4 c1 = __ldcs(&C4[base + j0 + 256]);
        float4 c2 = __ldcs(&C4[base + j0 + 512]);
        float4 c3 = __ldcs(&C4[base + j0 + 768]);
        uint2 k0 = __ldcg(&K2[base + j0]);
        uint2 k1 = __ldcg(&K2[base + j0 + 256]);
        uint2 k2 = __ldcg(&K2[base + j0 + 512]);
        uint2 k3 = __ldcg(&K2[base + j0 + 768]);
#define DOT1(jj, cc, kk)                                                      \
        {                                                                      \
            const int row = (jj) >> 8;                                         \
            const int col4 = (jj) & 255;                                       \
            const float uu = s_u[row];                                         \
            float2 ka = __half22float2(*reinterpret_cast<const __half2*>(&kk.x)); \
            float2 kb = __half22float2(*reinterpret_cast<const __half2*>(&kk.y)); \
            float4 t;                                                          \
            t.x = uu * ka.x * s_v[col4 * 4 + 0];                               \
            t.y = uu * ka.y * s_v[col4 * 4 + 1];                               \
            t.z = uu * kb.x * s_v[col4 * 4 + 2];                               \
            t.w = uu * kb.y * s_v[col4 * 4 + 3];                               \
            __stcs(&T4[base + (jj)], t);                                       \
            local += cc.x * t.x + cc.y * t.y + cc.z * t.z + cc.w * t.w;        \
        }
        DOT1(j0, c0, k0)
        DOT1(j0 + 256, c1, k1)
        DOT1(j0 + 512, c2, k2)
        DOT1(j0 + 768, c3, k3)
    }

    __shared__ int s_last;
    s_red[tid] = local;
    __syncthreads();
#pragma unroll
    for (int s = 128; s; s >>= 1) {
        if (tid < s) s_red[tid] += s_red[tid + s];
        __syncthreads();
    }
    if (tid == 0) {
        __stcg(&g_part[bid], s_red[0]);
        __threadfence();
        unsigned prev = atomicAdd(&g_cnt[b], 1u);
        s_last = (prev == 31) ? 1 : 0;
    }
    __syncthreads();

    if (s_last) {
        if (tid < 32) s_red[tid] = __ldcg(&g_part[b * 32 + tid]);
        __syncthreads();
        if (tid == 0) {
            float s = 0.0f;
#pragma unroll
            for (int i = 0; i < 32; ++i) s += s_red[i];
            outD[b] = s;
        }
    }
}

// ---------------- launch ----------------
extern "C" void kernel_launch(void* const* d_in, const int* in_sizes, int n_in,
                              void* d_out, int out_size) {
    (void)in_sizes; (void)n_in; (void)out_size;
    const float* C = (const float*)d_in[0];
    const float* d1 = (const float*)d_in[1];
    const float* d2 = (const float*)d_in[2];

    float* out = (float*)d_out;
    float* out_dists = out;                                  // [32]
    float* out_C = out + NB;                                 // [32,1024,1024]
    float* out_T = out_C + (size_t)NB * NN * NM;             // [32,1024,1024]

    prep_kernel<<<2048, 256>>>(reinterpret_cast<const float4*>(C),
                               reinterpret_cast<float4*>(out_C));
    sink_iter<<<NB * 4, 512>>>(d1, d2);
    finalize_kernel<<<NB * 32, 256>>>(reinterpret_cast<const float4*>(C),
                                      reinterpret_cast<float4*>(out_T), out_dists);
}

// round 11
// speedup vs baseline: 1.1462x; 1.1462x over previous
#include <cuda_runtime.h>
#include <cuda_fp16.h>
#include <cstdint>

#define NB 32
#define NN 1024
#define NM 1024
#define NITER 500
#define CONV_TOL 2e-3f

// ---------------- device scratch (allocation-free) ----------------
// K' = fp16(256 * exp(-10*C)); scale keeps all values in fp16 normal range.
static __device__ __align__(128) __half g_K[(size_t)NB * NN * NM]; // 64 MB fp16
static __device__ __align__(16) float g_u[NB * NN];   // u' = u/256 (scale-invariant outputs)
static __device__ __align__(16) float g_v[NB * NM];
static __device__ __align__(16) float g_part[NB * 32];
static __device__ __align__(16) int g_flag[NB * 4];
static __device__ __align__(16) unsigned g_cnt[NB];

__device__ __forceinline__ void cluster_sync_() {
    asm volatile("barrier.cluster.arrive.aligned;\n\t"
                 "barrier.cluster.wait.aligned;" ::: "memory");
}

// 256*exp(-10c) = exp(-10c + ln 256)
__device__ __forceinline__ uint2 pack_kf4(float4 c) {
    const float LN256 = 5.545177444479562f;
    float k0 = __expf(fmaf(-10.0f, c.x, LN256));
    float k1 = __expf(fmaf(-10.0f, c.y, LN256));
    float k2 = __expf(fmaf(-10.0f, c.z, LN256));
    float k3 = __expf(fmaf(-10.0f, c.w, LN256));
    __half2 h01 = __floats2half2_rn(k0, k1);
    __half2 h23 = __floats2half2_rn(k2, k3);
    uint2 o;
    o.x = *reinterpret_cast<unsigned*>(&h01);
    o.y = *reinterpret_cast<unsigned*>(&h23);
    return o;
}

// ---------------- precompute: K' fp16, u0 = 1, C passthrough ----------------
__global__ void prep_kernel(const float4* __restrict__ C4, float4* __restrict__ outC4) {
    const size_t total4 = (size_t)NB * NN * NM / 4;
    const size_t stride = (size_t)gridDim.x * blockDim.x;
    const size_t gtid = (size_t)blockIdx.x * blockDim.x + threadIdx.x;
    uint2* K2 = reinterpret_cast<uint2*>(g_K);
    for (size_t i = gtid; i < total4; i += 4 * stride) {
        float4 c0 = __ldcs(&C4[i]);
        float4 c1 = __ldcs(&C4[i + stride]);
        float4 c2 = __ldcs(&C4[i + 2 * stride]);
        float4 c3 = __ldcs(&C4[i + 3 * stride]);
        __stcs(&outC4[i], c0);
        __stcs(&outC4[i + stride], c1);
        __stcs(&outC4[i + 2 * stride], c2);
        __stcs(&outC4[i + 3 * stride], c3);
        K2[i] = pack_kf4(c0);
        K2[i + stride] = pack_kf4(c1);
        K2[i + 2 * stride] = pack_kf4(c2);
        K2[i + 3 * stride] = pack_kf4(c3);
    }
    for (size_t j = gtid; j < (size_t)NB * NN; j += stride)
        g_u[j] = 1.0f;
    if (gtid < NB) g_cnt[gtid] = 0;
}

// ---------------- persistent Sinkhorn iteration kernel ----------------
// grid = 128 CTAs x 512 threads, cluster (4,1,1): 4 CTAs per batch.
extern "C" __global__ void __cluster_dims__(4, 1, 1) __launch_bounds__(512, 1)
sink_iter(const float* __restrict__ d1, const float* __restrict__ d2) {
    __shared__ float s_vec[NM];
    __shared__ float s_red[16 * 256];
    __shared__ float s_uown[256];
    __shared__ int s_flag;
    __shared__ int s_break;

    const int b = blockIdx.x >> 2;
    const int cr = blockIdx.x & 3;
    const int tid = threadIdx.x;
    const int lane = tid & 31;
    const int warp = tid >> 5;

    const __half* Kbatch = g_K + (size_t)b * NN * NM;
    const float* d1b = d1 + b * NN;
    const float* d2b = d2 + b * NM;
    const int mbase = cr * 256;
    const int nbase = cr * 256;

    for (int it = 0; it < NITER; ++it) {
        // ---- Phase A: v[mbase + 0..255] = d2 / (K'^T u) ----
        for (int i = tid; i < NN; i += 512) s_vec[i] = __ldcg(&g_u[b * NN + i]);
        __syncthreads();
        if (tid < 256) s_uown[tid] = s_vec[nbase + tid];
        if (tid == 0) s_flag = 0;
        {
            const __half* Kc = Kbatch + mbase + lane * 8;
            float acc[8];
#pragma unroll
            for (int j = 0; j < 8; ++j) acc[j] = 0.0f;
            for (int n = warp; n < NN; n += 64) {
                uint4 kv0 = *reinterpret_cast<const uint4*>(Kc + (size_t)(n) * NM);
                uint4 kv1 = *reinterpret_cast<const uint4*>(Kc + (size_t)(n + 16) * NM);
                uint4 kv2 = *reinterpret_cast<const uint4*>(Kc + (size_t)(n + 32) * NM);
                uint4 kv3 = *reinterpret_cast<const uint4*>(Kc + (size_t)(n + 48) * NM);
                float u0 = s_vec[n];
                float u1 = s_vec[n + 16];
                float u2 = s_vec[n + 32];
                float u3 = s_vec[n + 48];
#define FMA8(kv, uu)                                                              \
                {                                                                  \
                    float2 f0 = __half22float2(*reinterpret_cast<const __half2*>(&kv.x)); \
                    float2 f1 = __half22float2(*reinterpret_cast<const __half2*>(&kv.y)); \
                    float2 f2 = __half22float2(*reinterpret_cast<const __half2*>(&kv.z)); \
                    float2 f3 = __half22float2(*reinterpret_cast<const __half2*>(&kv.w)); \
                    acc[0] = fmaf(f0.x, uu, acc[0]);                               \
                    acc[1] = fmaf(f0.y, uu, acc[1]);                               \
                    acc[2] = fmaf(f1.x, uu, acc[2]);                               \
                    acc[3] = fmaf(f1.y, uu, acc[3]);                               \
                    acc[4] = fmaf(f2.x, uu, acc[4]);                               \
                    acc[5] = fmaf(f2.y, uu, acc[5]);                               \
                    acc[6] = fmaf(f3.x, uu, acc[6]);                               \
                    acc[7] = fmaf(f3.y, uu, acc[7]);                               \
                }
                FMA8(kv0, u0)
                FMA8(kv1, u1)
                FMA8(kv2, u2)
                FMA8(kv3, u3)
            }
#pragma unroll
            for (int j = 0; j < 8; ++j) s_red[warp * 256 + lane * 8 + j] = acc[j];
        }
        __syncthreads();
        if (tid < 256) {
            float s = 0.0f;
#pragma unroll
            for (int g = 0; g < 16; ++g) s += s_red[g * 256 + tid];
            float v = d2b[mbase + tid] / s;
            __stcg(&g_v[b * NM + mbase + tid], v);
        }
        __syncthreads();
        cluster_sync_();

        // ---- Phase B: u[nbase + 0..255] = d1 / (K' v) ----
        for (int i = tid; i < NM; i += 512) s_vec[i] = __ldcg(&g_v[b * NM + i]);
        __syncthreads();
        {
            const int row0w = nbase + warp * 16;
#pragma unroll
            for (int g = 0; g < 4; ++g) {
                const int r0 = row0w + g * 4;
                const __half* Kr = Kbatch + (size_t)r0 * NM + lane * 8;
                float a[4] = {0.0f, 0.0f, 0.0f, 0.0f};
#pragma unroll
                for (int k = 0; k < 4; ++k) {
                    const int c0 = k * 256 + lane * 8;
                    float4 va = *reinterpret_cast<const float4*>(&s_vec[c0]);
                    float4 vb = *reinterpret_cast<const float4*>(&s_vec[c0 + 4]);
                    uint4 kq0 = *reinterpret_cast<const uint4*>(Kr + (size_t)0 * NM + k * 256);
                    uint4 kq1 = *reinterpret_cast<const uint4*>(Kr + (size_t)1 * NM + k * 256);
                    uint4 kq2 = *reinterpret_cast<const uint4*>(Kr + (size_t)2 * NM + k * 256);
                    uint4 kq3 = *reinterpret_cast<const uint4*>(Kr + (size_t)3 * NM + k * 256);
#define ROWFMA(r, kv)                                                              \
                    {                                                               \
                        float2 f0 = __half22float2(*reinterpret_cast<const __half2*>(&kv.x)); \
                        float2 f1 = __half22float2(*reinterpret_cast<const __half2*>(&kv.y)); \
                        float2 f2 = __half22float2(*reinterpret_cast<const __half2*>(&kv.z)); \
                        float2 f3 = __half22float2(*reinterpret_cast<const __half2*>(&kv.w)); \
                        float ar = a[r];                                            \
                        ar = fmaf(f0.x, va.x, ar);                                  \
                        ar = fmaf(f0.y, va.y, ar);                                  \
                        ar = fmaf(f1.x, va.z, ar);                                  \
                        ar = fmaf(f1.y, va.w, ar);                                  \
                        ar = fmaf(f2.x, vb.x, ar);                                  \
                        ar = fmaf(f2.y, vb.y, ar);                                  \
                        ar = fmaf(f3.x, vb.z, ar);                                  \
                        ar = fmaf(f3.y, vb.w, ar);                                  \
                        a[r] = ar;                                                  \
                    }
                    ROWFMA(0, kq0)
                    ROWFMA(1, kq1)
                    ROWFMA(2, kq2)
                    ROWFMA(3, kq3)
                }
#pragma unroll
                for (int off = 16; off; off >>= 1) {
#pragma unroll
                    for (int r = 0; r < 4; ++r) a[r] += __shfl_xor_sync(0xffffffffu, a[r], off);
                }
                if (lane < 4) {
                    float un = d1b[r0 + lane] / a[lane];
                    __stcg(&g_u[b * NN + r0 + lane], un);
                    float uold = s_uown[warp * 16 + g * 4 + lane];
                    if (fabsf(un - uold) > CONV_TOL * fabsf(un)) s_flag = 1;
                }
            }
        }
        __syncthreads();
        if (tid == 0) __stcg(&g_flag[blockIdx.x], s_flag);
        cluster_sync_();
        if (tid == 0) {
            int base = (b << 2);
            int f = __ldcg(&g_flag[base]) | __ldcg(&g_flag[base + 1]) |
                    __ldcg(&g_flag[base + 2]) | __ldcg(&g_flag[base + 3]);
            s_break = (f == 0);
        }
        __syncthreads();
        if (s_break) break;
    }
}

// ---------------- finalize: T = u'*K'*v, C recovered from K' (NO C read!) ----------------
// dists = sum(C~ * T) with C~ = (ln256 - ln K')/10; K' is L2-hot from the sink loop.
// Traffic: 64MB L2 read + 128MB DRAM write only.
__global__ void __launch_bounds__(256) finalize_kernel(float4* __restrict__ T4,
                                                       float* __restrict__ outD) {
    const int bid = blockIdx.x;
    const int b = bid >> 5;
    const int chunk = bid & 31;
    const int tid = threadIdx.x;
    const float LN256 = 5.545177444479562f;

    __shared__ float s_u[32];
    __shared__ float s_v[NM];
    __shared__ float s_red[256];

    if (tid < 32) s_u[tid] = __ldcg(&g_u[b * NN + chunk * 32 + tid]);
    for (int i = tid; i < NM; i += 256) s_v[i] = __ldcg(&g_v[b * NM + i]);
    __syncthreads();

    const size_t base = (size_t)b * (NN * NM / 4) + (size_t)chunk * 8192;
    const uint2* K2 = reinterpret_cast<const uint2*>(g_K);
    float local = 0.0f;
#pragma unroll
    for (int step = 0; step < 8; ++step) {
        const int j0 = step * 1024 + tid;
        uint2 k0 = __ldcg(&K2[base + j0]);
        uint2 k1 = __ldcg(&K2[base + j0 + 256]);
        uint2 k2 = __ldcg(&K2[base + j0 + 512]);
        uint2 k3 = __ldcg(&K2[base + j0 + 768]);
#define DOT1(jj, kk)                                                           \
        {                                                                      \
            const int row = (jj) >> 8;                                         \
            const int col4 = (jj) & 255;                                       \
            const float uu = s_u[row];                                         \
            float2 ka = __half22float2(*reinterpret_cast<const __half2*>(&kk.x)); \
            float2 kb = __half22float2(*reinterpret_cast<const __half2*>(&kk.y)); \
            float4 t;                                                          \
            t.x = uu * ka.x * s_v[col4 * 4 + 0];                               \
            t.y = uu * ka.y * s_v[col4 * 4 + 1];                               \
            t.z = uu * kb.x * s_v[col4 * 4 + 2];                               \
            t.w = uu * kb.y * s_v[col4 * 4 + 3];                               \
            __stcs(&T4[base + (jj)], t);                                       \
            float cx = (LN256 - __logf(ka.x)) * 0.1f;                          \
            float cy = (LN256 - __logf(ka.y)) * 0.1f;                          \
            float cz = (LN256 - __logf(kb.x)) * 0.1f;                          \
            float cw = (LN256 - __logf(kb.y)) * 0.1f;                          \
            local += cx * t.x + cy * t.y + cz * t.z + cw * t.w;                \
        }
        DOT1(j0, k0)
        DOT1(j0 + 256, k1)
        DOT1(j0 + 512, k2)
        DOT1(j0 + 768, k3)
    }

    __shared__ int s_last;
    s_red[tid] = local;
    __syncthreads();
#pragma unroll
    for (int s = 128; s; s >>= 1) {
        if (tid < s) s_red[tid] += s_red[tid + s];
        __syncthreads();
    }
    if (tid == 0) {
        __stcg(&g_part[bid], s_red[0]);
        __threadfence();
        unsigned prev = atomicAdd(&g_cnt[b], 1u);
        s_last = (prev == 31) ? 1 : 0;
    }
    __syncthreads();

    if (s_last) {
        if (tid < 32) s_red[tid] = __ldcg(&g_part[b * 32 + tid]);
        __syncthreads();
        if (tid == 0) {
            float s = 0.0f;
#pragma unroll
            for (int i = 0; i < 32; ++i) s += s_red[i];
            outD[b] = s;
        }
    }
}

// ---------------- launch ----------------
extern "C" void kernel_launch(void* const* d_in, const int* in_sizes, int n_in,
                              void* d_out, int out_size) {
    (void)in_sizes; (void)n_in; (void)out_size;
    const float* C = (const float*)d_in[0];
    const float* d1 = (const float*)d_in[1];
    const float* d2 = (const float*)d_in[2];

    float* out = (float*)d_out;
    float* out_dists = out;                                  // [32]
    float* out_C = out + NB;                                 // [32,1024,1024]
    float* out_T = out_C + (size_t)NB * NN * NM;             // [32,1024,1024]

    prep_kernel<<<2048, 256>>>(reinterpret_cast<const float4*>(C),
                               reinterpret_cast<float4*>(out_C));
    sink_iter<<<NB * 4, 512>>>(d1, d2);
    finalize_kernel<<<NB * 32, 256>>>(reinterpret_cast<float4*>(out_T), out_dists);
}